// round 5
// baseline (speedup 1.0000x reference)
#include <cuda_runtime.h>
#include <math.h>

#define NROW 512
#define CZ   128
#define NPAIR (NROW * NROW) /* 262144 */

typedef unsigned int u32;

// ---------------- device scratch ----------------
__device__ float g_A[(size_t)CZ * NPAIR];   // a, [c][i*512+k]
__device__ float g_B[(size_t)CZ * NPAIR];   // b, [c][j*512+k]
__device__ float g_G[(size_t)CZ * NPAIR];   // gate, [c][pair]
__device__ float g_T[(size_t)CZ * NPAIR];   // t, [c][i*512+j]
__device__ float g_wt[6 * 128 * 128];       // weights, pair layout [n][slots]
// img order: 0 w_ap, 1 w_ag, 2 w_bp, 3 w_bg, 4 w_g, 5 w_z

// ---------------- helpers ----------------
__device__ __forceinline__ float tf32r(float x) {
    float r;
    asm("cvt.rna.tf32.f32 %0, %1;" : "=f"(r) : "f"(x));
    return r;
}
__device__ __forceinline__ float wsum(float v) {
#pragma unroll
    for (int o = 16; o; o >>= 1) v += __shfl_xor_sync(0xffffffffu, v, o);
    return v;
}
__device__ __forceinline__ float sigm(float x) {
    return 1.0f / (1.0f + __expf(-x));
}
__device__ __forceinline__ void mma8(float* d, const u32* a, const u32* b) {
    asm volatile(
        "mma.sync.aligned.m16n8k8.row.col.f32.tf32.tf32.f32 "
        "{%0,%1,%2,%3}, {%4,%5,%6,%7}, {%8,%9}, {%0,%1,%2,%3};"
        : "+f"(d[0]), "+f"(d[1]), "+f"(d[2]), "+f"(d[3])
        : "r"(a[0]), "r"(a[1]), "r"(a[2]), "r"(a[3]), "r"(b[0]), "r"(b[1]));
}

// ============================================================================
// prep: transpose + tf32-round weights into pair layout:
// g_wt[img][n*128 + (k>>3)*8 + (k&3)*2 + ((k&4)>>2)]
// ============================================================================
__global__ void prep_w(const float* __restrict__ wap, const float* __restrict__ wag,
                       const float* __restrict__ wbp, const float* __restrict__ wbg,
                       const float* __restrict__ wg,  const float* __restrict__ wz) {
    int img = blockIdx.y;
    int lin = blockIdx.x * 256 + threadIdx.x;
    int n = lin >> 7, k = lin & 127;
    const float* s;
    switch (img) {
        case 0: s = wap; break; case 1: s = wag; break;
        case 2: s = wbp; break; case 3: s = wbg; break;
        case 4: s = wg;  break; default: s = wz; break;
    }
    int pos = n * 128 + (k >> 3) * 8 + (k & 3) * 2 + ((k & 4) >> 2);
    g_wt[img * 16384 + pos] = tf32r(s[k * 128 + n]);
}

// ============================================================================
// GEMM core: pair layout. A stride 68 float2/row, W stride 68 float2/row.
// Warp tile 32m x (NT*8)n, K=128. A-frag prefetch across ks.
// ============================================================================
template <int NT>
__device__ __forceinline__ void gemm_pair(const float2* __restrict__ As2,
                                          const float2* __restrict__ Ws2,
                                          int aoff0, const int* __restrict__ boffs,
                                          float acc[2][16][4]) {
    float2 ac[2][2];
#pragma unroll
    for (int mt = 0; mt < 2; ++mt) {
        ac[mt][0] = As2[aoff0 + mt * 1088];
        ac[mt][1] = As2[aoff0 + mt * 1088 + 544];
    }
#pragma unroll
    for (int ks = 0; ks < 16; ++ks) {
        float2 b[NT];
#pragma unroll
        for (int nt = 0; nt < NT; ++nt) b[nt] = Ws2[boffs[nt] + ks * 4];
        float2 an[2][2];
        if (ks < 15) {
#pragma unroll
            for (int mt = 0; mt < 2; ++mt) {
                an[mt][0] = As2[aoff0 + (ks + 1) * 4 + mt * 1088];
                an[mt][1] = As2[aoff0 + (ks + 1) * 4 + mt * 1088 + 544];
            }
        }
        u32 aa[2][4];
#pragma unroll
        for (int mt = 0; mt < 2; ++mt) {
            aa[mt][0] = __float_as_uint(ac[mt][0].x);
            aa[mt][1] = __float_as_uint(ac[mt][1].x);
            aa[mt][2] = __float_as_uint(ac[mt][0].y);
            aa[mt][3] = __float_as_uint(ac[mt][1].y);
        }
#pragma unroll
        for (int nt = 0; nt < NT; ++nt) {
            u32 bb[2] = { __float_as_uint(b[nt].x), __float_as_uint(b[nt].y) };
            mma8(acc[0][nt], aa[0], bb);
            mma8(acc[1][nt], aa[1], bb);
        }
#pragma unroll
        for (int mt = 0; mt < 2; ++mt) { ac[mt][0] = an[mt][0]; ac[mt][1] = an[mt][1]; }
    }
}

__device__ __forceinline__ void zero_acc(float acc[2][16][4]) {
#pragma unroll
    for (int i = 0; i < 2; ++i)
#pragma unroll
        for (int j = 0; j < 16; ++j)
#pragma unroll
            for (int q = 0; q < 4; ++q) acc[i][j][q] = 0.f;
}

// load stacked weight image [imgP(128 rows); imgG(128 rows)] into Ws (stride 34 f4)
__device__ __forceinline__ void loadW2(float* __restrict__ Ws, int imgP, int imgG, int tid) {
#pragma unroll
    for (int it = 0; it < 32; ++it) {
        int lin = it * 256 + tid;
        int row = lin >> 5, q = lin & 31;
        const float4* s = (const float4*)(g_wt +
            (row < 128 ? imgP * 16384 + row * 128 : imgG * 16384 + (row - 128) * 128));
        ((float4*)Ws)[row * 34 + q] = s[q];
    }
}
__device__ __forceinline__ void loadW1(float* __restrict__ Ws, int img, int tid) {
#pragma unroll
    for (int it = 0; it < 16; ++it) {
        int lin = it * 256 + tid;
        int row = lin >> 5, q = lin & 31;
        ((float4*)Ws)[row * 34 + q] = ((const float4*)(g_wt + img * 16384 + row * 128))[q];
    }
}

// epilogue: dst[c][pair] = tf32r(sigm(gate)*(proj)); gate = acc[][nt+8]
__device__ __forceinline__ void epi_ab(const float acc[2][16][4],
                                       const float* __restrict__ bp,
                                       const float* __restrict__ bg,
                                       float* __restrict__ dst, size_t pair0,
                                       int m0, int n0, int g, int t) {
#pragma unroll
    for (int mt = 0; mt < 2; ++mt) {
        int r = m0 + mt * 16 + g;
#pragma unroll
        for (int nt = 0; nt < 8; ++nt) {
            int c = n0 + nt * 8 + 2 * t;
            float2 bpv = *(const float2*)(bp + c);
            float2 bgv = *(const float2*)(bg + c);
            float* d0 = dst + (size_t)c * NPAIR + pair0;
            float* d1 = dst + (size_t)(c + 1) * NPAIR + pair0;
            const float* P = acc[mt][nt];
            const float* G = acc[mt][nt + 8];
            d0[r]     = tf32r(sigm(G[0] + bgv.x) * (P[0] + bpv.x));
            d1[r]     = tf32r(sigm(G[1] + bgv.y) * (P[1] + bpv.y));
            d0[r + 8] = tf32r(sigm(G[2] + bgv.x) * (P[2] + bpv.x));
            d1[r + 8] = tf32r(sigm(G[3] + bgv.y) * (P[3] + bpv.y));
        }
    }
}

// ============================================================================
// proj_all: LN once, then 3 GEMM passes (ap||ag, bp||bg stacked N=256; g N=128)
// ============================================================================
__global__ __launch_bounds__(256) void proj_all_kernel(
    const float* __restrict__ z,
    const float* __restrict__ lnw, const float* __restrict__ lnb,
    const float* __restrict__ b_ap, const float* __restrict__ b_ag,
    const float* __restrict__ b_bp, const float* __restrict__ b_bg,
    const float* __restrict__ b_g)
{
    extern __shared__ float smf[];
    float* As = smf;                 // 128 rows x 136 floats (pair, stride 68 f2)
    float* Ws = smf + 128 * 136;     // 256 rows x 136 floats
    const int tid = threadIdx.x;
    const int wid = tid >> 5, lane = tid & 31;
    const int g = lane >> 2, t = lane & 3;
    const int m0 = (wid & 3) * 32, n0 = (wid >> 2) * 64;
    const size_t pair0 = (size_t)blockIdx.x * 128;

    // ---- LN -> As (pair layout) ----
    {
        float4 lw = ((const float4*)lnw)[lane];
        float4 lb = ((const float4*)lnb)[lane];
#pragma unroll 2
        for (int r = 0; r < 16; ++r) {
            int row = wid * 16 + r;
            float4 x = ((const float4*)(z + (pair0 + row) * (size_t)CZ))[lane];
            float m = wsum(x.x + x.y + x.z + x.w) * (1.0f / 128.0f);
            float dx = x.x - m, dy = x.y - m, dz = x.z - m, dw = x.w - m;
            float var = wsum(dx * dx + dy * dy + dz * dz + dw * dw) * (1.0f / 128.0f);
            float rs = rsqrtf(var + 1e-5f);
            float* dst = As + row * 136 + (lane >> 1) * 8 + (lane & 1);
            dst[0] = tf32r(dx * rs * lw.x + lb.x);
            dst[2] = tf32r(dy * rs * lw.y + lb.y);
            dst[4] = tf32r(dz * rs * lw.z + lb.z);
            dst[6] = tf32r(dw * rs * lw.w + lb.w);
        }
    }

    int boffs[16];
#pragma unroll
    for (int nt = 0; nt < 16; ++nt)
        boffs[nt] = (n0 + (nt & 7) * 8 + g + ((nt >> 3) << 7)) * 68 + t;
    const int aoff0 = (m0 + g) * 68 + t;
    const float2* As2 = (const float2*)As;
    const float2* Ws2 = (const float2*)Ws;

    float acc[2][16][4];

    // pass A: w_ap || w_ag
    loadW2(Ws, 0, 1, tid);
    __syncthreads();
    zero_acc(acc);
    gemm_pair<16>(As2, Ws2, aoff0, boffs, acc);
    __syncthreads();
    loadW2(Ws, 2, 3, tid);
    epi_ab(acc, b_ap, b_ag, g_A, pair0, m0, n0, g, t);
    __syncthreads();

    // pass B: w_bp || w_bg
    zero_acc(acc);
    gemm_pair<16>(As2, Ws2, aoff0, boffs, acc);
    __syncthreads();
    loadW1(Ws, 4, tid);
    epi_ab(acc, b_bp, b_bg, g_B, pair0, m0, n0, g, t);
    __syncthreads();

    // pass G: w_g (N=128)
    zero_acc(acc);
    gemm_pair<8>(As2, Ws2, aoff0, boffs, acc);
#pragma unroll
    for (int mt = 0; mt < 2; ++mt) {
        int r = m0 + mt * 16 + g;
#pragma unroll
        for (int nt = 0; nt < 8; ++nt) {
            int c = n0 + nt * 8 + 2 * t;
            float2 bgv = *(const float2*)(b_g + c);
            float* d0 = g_G + (size_t)c * NPAIR + pair0;
            float* d1 = g_G + (size_t)(c + 1) * NPAIR + pair0;
            const float* P = acc[mt][nt];
            d0[r]     = sigm(P[0] + bgv.x);
            d1[r]     = sigm(P[1] + bgv.y);
            d0[r + 8] = sigm(P[2] + bgv.x);
            d1[r + 8] = sigm(P[3] + bgv.y);
        }
    }
}

// ============================================================================
// tri: t[c][i][j] = sum_k a[c][i][k]*b[c][j][k]; 128x128 tile, K=512,
// K chunks of 32, double-buffered pair-layout smem (stride 18 f2).
// ============================================================================
__global__ __launch_bounds__(256) void tri_kernel()
{
    extern __shared__ float smf[];
    float2* Ab[2] = { (float2*)smf,        (float2*)smf + 2304 };
    float2* Bb[2] = { (float2*)smf + 4608, (float2*)smf + 6912 };
    const int tid = threadIdx.x;
    const int wid = tid >> 5, lane = tid & 31;
    const int g = lane >> 2, t = lane & 3;
    const int m0 = (wid & 3) * 32, n0 = (wid >> 2) * 64;
    const int c  = blockIdx.z;
    const int i0 = blockIdx.y * 128;
    const int j0 = blockIdx.x * 128;
    const float* __restrict__ asrc = g_A + (size_t)c * NPAIR + (size_t)i0 * NROW;
    const float* __restrict__ bsrc = g_B + (size_t)c * NPAIR + (size_t)j0 * NROW;

    // stage chunk 0
#pragma unroll
    for (int it = 0; it < 4; ++it) {
        int lin = it * 256 + tid, row = lin >> 3, q = lin & 7;
        float4 va = *(const float4*)(asrc + (size_t)row * NROW + q * 4);
        float4 vb = *(const float4*)(bsrc + (size_t)row * NROW + q * 4);
        float* pa = (float*)Ab[0] + row * 36 + (q >> 1) * 8 + (q & 1);
        float* pb = (float*)Bb[0] + row * 36 + (q >> 1) * 8 + (q & 1);
        pa[0] = va.x; pa[2] = va.y; pa[4] = va.z; pa[6] = va.w;
        pb[0] = vb.x; pb[2] = vb.y; pb[4] = vb.z; pb[6] = vb.w;
    }
    __syncthreads();

    float acc[2][8][4];
#pragma unroll
    for (int i = 0; i < 2; ++i)
#pragma unroll
        for (int j = 0; j < 8; ++j)
#pragma unroll
            for (int q = 0; q < 4; ++q) acc[i][j][q] = 0.f;

    const int aoff = (m0 + g) * 18 + t;   // f2 units; +mt*288, +144 for row+8
    int boff[8];
#pragma unroll
    for (int nt = 0; nt < 8; ++nt) boff[nt] = (n0 + nt * 8 + g) * 18 + t;

#pragma unroll 1
    for (int kc = 0; kc < 16; ++kc) {
        const float2* A = Ab[kc & 1];
        const float2* B = Bb[kc & 1];
        float4 ra[4], rb[4];
        if (kc < 15) {
            int k0 = (kc + 1) * 32;
#pragma unroll
            for (int it = 0; it < 4; ++it) {
                int lin = it * 256 + tid, row = lin >> 3, q = lin & 7;
                ra[it] = *(const float4*)(asrc + (size_t)row * NROW + k0 + q * 4);
                rb[it] = *(const float4*)(bsrc + (size_t)row * NROW + k0 + q * 4);
            }
        }
#pragma unroll
        for (int ks = 0; ks < 4; ++ks) {
            float2 a0[2][2], b0[8];
#pragma unroll
            for (int mt = 0; mt < 2; ++mt) {
                a0[mt][0] = A[aoff + ks * 4 + mt * 288];
                a0[mt][1] = A[aoff + ks * 4 + mt * 288 + 144];
            }
#pragma unroll
            for (int nt = 0; nt < 8; ++nt) b0[nt] = B[boff[nt] + ks * 4];
            u32 aa[2][4];
#pragma unroll
            for (int mt = 0; mt < 2; ++mt) {
                aa[mt][0] = __float_as_uint(a0[mt][0].x);
                aa[mt][1] = __float_as_uint(a0[mt][1].x);
                aa[mt][2] = __float_as_uint(a0[mt][0].y);
                aa[mt][3] = __float_as_uint(a0[mt][1].y);
            }
#pragma unroll
            for (int nt = 0; nt < 8; ++nt) {
                u32 bb[2] = { __float_as_uint(b0[nt].x), __float_as_uint(b0[nt].y) };
                mma8(acc[0][nt], aa[0], bb);
                mma8(acc[1][nt], aa[1], bb);
            }
        }
        if (kc < 15) {
            int nb = (kc + 1) & 1;
#pragma unroll
            for (int it = 0; it < 4; ++it) {
                int lin = it * 256 + tid, row = lin >> 3, q = lin & 7;
                float* pa = (float*)Ab[nb] + row * 36 + (q >> 1) * 8 + (q & 1);
                float* pb = (float*)Bb[nb] + row * 36 + (q >> 1) * 8 + (q & 1);
                pa[0] = ra[it].x; pa[2] = ra[it].y; pa[4] = ra[it].z; pa[6] = ra[it].w;
                pb[0] = rb[it].x; pb[2] = rb[it].y; pb[4] = rb[it].z; pb[6] = rb[it].w;
            }
            __syncthreads();
        }
    }

    float* __restrict__ tdst = g_T + (size_t)c * NPAIR;
#pragma unroll
    for (int mt = 0; mt < 2; ++mt) {
        int r = i0 + m0 + mt * 16 + g;
#pragma unroll
        for (int nt = 0; nt < 8; ++nt) {
            int cl = j0 + n0 + nt * 8 + 2 * t;
            *(float2*)(tdst + (size_t)r * NROW + cl) =
                make_float2(acc[mt][nt][0], acc[mt][nt][1]);
            *(float2*)(tdst + (size_t)(r + 8) * NROW + cl) =
                make_float2(acc[mt][nt][2], acc[mt][nt][3]);
        }
    }
}

// ============================================================================
// final: out[pair][cz] = g * (LN_c(t) @ Wz + bz)
// ============================================================================
__global__ __launch_bounds__(256) void final_kernel(
    const float* __restrict__ lnw, const float* __restrict__ lnb,
    const float* __restrict__ bz, float* __restrict__ out)
{
    extern __shared__ float smf[];
    float* As = smf;                       // [128 c][136 pair] k-major
    float* Ws = As + 128 * 136;            // pair layout, stride 68 f2
    float* MS = Ws + 128 * 136;
    float* RS = MS + 128;
    float* PS = RS + 128;
    float* PQ = PS + 256;
    const int tid = threadIdx.x;
    const int wid = tid >> 5, lane = tid & 31;
    const int g = lane >> 2, t = lane & 3;
    const int m0 = (wid & 3) * 32, n0 = (wid >> 2) * 64;
    const size_t pair0 = (size_t)blockIdx.x * 128;

    loadW1(Ws, 5, tid);

    // pass1: gather t (coalesced per c), partial stats per pair
    {
        const int p = tid & 127, ch = tid >> 7;
        float s = 0.f, q = 0.f;
#pragma unroll 4
        for (int cc = 0; cc < 64; ++cc) {
            int c = ch * 64 + cc;
            float v = g_T[(size_t)c * NPAIR + pair0 + p];
            As[c * 136 + p] = v;
            s += v; q += v * v;
        }
        PS[tid] = s; PQ[tid] = q;
    }
    __syncthreads();
    if (tid < 128) {
        float s = PS[tid] + PS[tid + 128];
        float q = PQ[tid] + PQ[tid + 128];
        float m = s * (1.0f / 128.0f);
        MS[tid] = m;
        RS[tid] = rsqrtf(fmaxf(q * (1.0f / 128.0f) - m * m, 0.f) + 1e-5f);
    }
    __syncthreads();

    // pass2: normalize in place
#pragma unroll 2
    for (int it = 0; it < 16; ++it) {
        int c = wid * 16 + it;
        float lw = __ldg(lnw + c), lb = __ldg(lnb + c);
#pragma unroll
        for (int sg = 0; sg < 4; ++sg) {
            int p = sg * 32 + lane;
            float x = As[c * 136 + p];
            As[c * 136 + p] = tf32r((x - MS[p]) * RS[p] * lw + lb);
        }
    }
    __syncthreads();

    float acc[2][8][4];
#pragma unroll
    for (int i = 0; i < 2; ++i)
#pragma unroll
        for (int j = 0; j < 8; ++j)
#pragma unroll
            for (int q = 0; q < 4; ++q) acc[i][j][q] = 0.f;

    const float2* Ws2 = (const float2*)Ws;
    int boff[8];
#pragma unroll
    for (int nt = 0; nt < 8; ++nt) boff[nt] = (n0 + nt * 8 + g) * 68 + t;

#pragma unroll 4
    for (int ks = 0; ks < 16; ++ks) {
        const int k0 = ks * 8;
        u32 af[2][4];
#pragma unroll
        for (int mt = 0; mt < 2; ++mt) {
            const float* ap = As + (k0 + t) * 136 + m0 + mt * 16 + g;
            af[mt][0] = __float_as_uint(ap[0]);
            af[mt][1] = __float_as_uint(ap[8]);
            af[mt][2] = __float_as_uint(ap[4 * 136]);
            af[mt][3] = __float_as_uint(ap[4 * 136 + 8]);
        }
#pragma unroll
        for (int nt = 0; nt < 8; ++nt) {
            float2 bv = Ws2[boff[nt] + ks * 4];
            u32 bb[2] = { __float_as_uint(bv.x), __float_as_uint(bv.y) };
            mma8(acc[0][nt], af[0], bb);
            mma8(acc[1][nt], af[1], bb);
        }
    }

#pragma unroll
    for (int mt = 0; mt < 2; ++mt) {
        int r = m0 + mt * 16 + g;
#pragma unroll
        for (int nt = 0; nt < 8; ++nt) {
            int c = n0 + nt * 8 + 2 * t;
            float2 bzv = *(const float2*)(bz + c);
            float gv00 = g_G[(size_t)c * NPAIR + pair0 + r];
            float gv01 = g_G[(size_t)(c + 1) * NPAIR + pair0 + r];
            float gv10 = g_G[(size_t)c * NPAIR + pair0 + r + 8];
            float gv11 = g_G[(size_t)(c + 1) * NPAIR + pair0 + r + 8];
            *(float2*)(out + (pair0 + r) * (size_t)CZ + c) =
                make_float2(gv00 * (acc[mt][nt][0] + bzv.x),
                            gv01 * (acc[mt][nt][1] + bzv.y));
            *(float2*)(out + (pair0 + r + 8) * (size_t)CZ + c) =
                make_float2(gv10 * (acc[mt][nt][2] + bzv.x),
                            gv11 * (acc[mt][nt][3] + bzv.y));
        }
    }
}

// ============================================================================
// kernel_launch
// ============================================================================
extern "C" void kernel_launch(void* const* d_in, const int* in_sizes, int n_in,
                              void* d_out, int out_size)
{
    const float* z        = (const float*)d_in[0];
    const float* ln_in_w  = (const float*)d_in[1];
    const float* ln_in_b  = (const float*)d_in[2];
    const float* ln_out_w = (const float*)d_in[3];
    const float* ln_out_b = (const float*)d_in[4];
    const float* w_ap     = (const float*)d_in[5];
    const float* b_ap     = (const float*)d_in[6];
    const float* w_ag     = (const float*)d_in[7];
    const float* b_ag     = (const float*)d_in[8];
    const float* w_bp     = (const float*)d_in[9];
    const float* b_bp     = (const float*)d_in[10];
    const float* w_bg     = (const float*)d_in[11];
    const float* b_bg     = (const float*)d_in[12];
    const float* w_g      = (const float*)d_in[13];
    const float* b_g      = (const float*)d_in[14];
    const float* w_z      = (const float*)d_in[15];
    const float* b_z      = (const float*)d_in[16];
    float* out = (float*)d_out;

    const int PROJ_SMEM = (128 * 136 + 256 * 136) * 4;              // 208896
    const int TRI_SMEM  = 4 * 2304 * 8;                             // 73728
    const int FIN_SMEM  = (128 * 136 * 2 + 128 * 2 + 512) * 4;      // 142336

    cudaFuncSetAttribute(proj_all_kernel, cudaFuncAttributeMaxDynamicSharedMemorySize, PROJ_SMEM);
    cudaFuncSetAttribute(tri_kernel,      cudaFuncAttributeMaxDynamicSharedMemorySize, TRI_SMEM);
    cudaFuncSetAttribute(final_kernel,    cudaFuncAttributeMaxDynamicSharedMemorySize, FIN_SMEM);

    dim3 pgrid(64, 6);
    prep_w<<<pgrid, 256>>>(w_ap, w_ag, w_bp, w_bg, w_g, w_z);

    proj_all_kernel<<<NPAIR / 128, 256, PROJ_SMEM>>>(
        z, ln_in_w, ln_in_b, b_ap, b_ag, b_bp, b_bg, b_g);

    dim3 tgrid(4, 4, 128);
    tri_kernel<<<tgrid, 256, TRI_SMEM>>>();

    final_kernel<<<NPAIR / 128, 256, FIN_SMEM>>>(ln_out_w, ln_out_b, b_z, out);
}

// round 6
// speedup vs baseline: 1.6196x; 1.6196x over previous
#include <cuda_runtime.h>
#include <math.h>

#define NROW 512
#define CZ   128
#define NPAIR (NROW * NROW) /* 262144 */

typedef unsigned int u32;

// ---------------- device scratch ----------------
__device__ float g_A[(size_t)CZ * NPAIR];   // a, [c][i*512+k]  (pair-k layout per row? no: plain k)
__device__ float g_B[(size_t)CZ * NPAIR];   // b, [c][j*512+k]
__device__ float g_G[(size_t)CZ * NPAIR];   // gate, [c][pair]
__device__ float g_T[(size_t)CZ * NPAIR];   // t, [c][i*512+j]
__device__ float g_wt[6 * 128 * 128];       // weights, pair layout [n][slots]
// img order: 0 w_ap, 1 w_ag, 2 w_bp, 3 w_bg, 4 w_g, 5 w_z

// ---------------- helpers ----------------
__device__ __forceinline__ float tf32r(float x) {
    float r;
    asm("cvt.rna.tf32.f32 %0, %1;" : "=f"(r) : "f"(x));
    return r;
}
__device__ __forceinline__ float wsum(float v) {
#pragma unroll
    for (int o = 16; o; o >>= 1) v += __shfl_xor_sync(0xffffffffu, v, o);
    return v;
}
__device__ __forceinline__ float sigm(float x) {
    return 1.0f / (1.0f + __expf(-x));
}
__device__ __forceinline__ void mma8(float* d, const u32* a, const u32* b) {
    asm volatile(
        "mma.sync.aligned.m16n8k8.row.col.f32.tf32.tf32.f32 "
        "{%0,%1,%2,%3}, {%4,%5,%6,%7}, {%8,%9}, {%0,%1,%2,%3};"
        : "+f"(d[0]), "+f"(d[1]), "+f"(d[2]), "+f"(d[3])
        : "r"(a[0]), "r"(a[1]), "r"(a[2]), "r"(a[3]), "r"(b[0]), "r"(b[1]));
}

// ============================================================================
// prep: transpose + tf32-round weights into pair layout:
// g_wt[img][n*128 + (k>>3)*8 + (k&3)*2 + ((k&4)>>2)]
// ============================================================================
__global__ void prep_w(const float* __restrict__ wap, const float* __restrict__ wag,
                       const float* __restrict__ wbp, const float* __restrict__ wbg,
                       const float* __restrict__ wg,  const float* __restrict__ wz) {
    int img = blockIdx.y;
    int lin = blockIdx.x * 256 + threadIdx.x;
    int n = lin >> 7, k = lin & 127;
    const float* s;
    switch (img) {
        case 0: s = wap; break; case 1: s = wag; break;
        case 2: s = wbp; break; case 3: s = wbg; break;
        case 4: s = wg;  break; default: s = wz; break;
    }
    int pos = n * 128 + (k >> 3) * 8 + (k & 3) * 2 + ((k & 4) >> 2);
    g_wt[img * 16384 + pos] = tf32r(s[k * 128 + n]);
}

// ============================================================================
// load a 64-row weight chunk (rows nb..nb+63 of image img) into Wc
// (row stride 136 floats = 34 float4; data 32 float4/row)
// ============================================================================
__device__ __forceinline__ void loadWc(float* __restrict__ Wc, int img, int nb, int tid) {
    const float4* src = (const float4*)(g_wt + img * 16384);
#pragma unroll
    for (int it = 0; it < 8; ++it) {
        int lin = it * 256 + tid;          // 0..2047
        int row = lin >> 5, q = lin & 31;
        ((float4*)Wc)[row * 34 + q] = src[(nb + row) * 32 + q];
    }
}

// GEMM: warp tile m16 x n64, K=128. As pair layout (stride 68 f2),
// Wc pair layout (64 rows, stride 68 f2). acc[8][4].
__device__ __forceinline__ void gemm64(const float2* __restrict__ As2,
                                       const float2* __restrict__ Wc2,
                                       int aoff, int g, int t, float acc[8][4]) {
#pragma unroll
    for (int i = 0; i < 8; ++i)
#pragma unroll
        for (int q = 0; q < 4; ++q) acc[i][q] = 0.f;
#pragma unroll
    for (int ks = 0; ks < 16; ++ks) {
        float2 a0 = As2[aoff + ks * 4];
        float2 a1 = As2[aoff + ks * 4 + 544];   // +8 rows
        u32 aa[4] = { __float_as_uint(a0.x), __float_as_uint(a1.x),
                      __float_as_uint(a0.y), __float_as_uint(a1.y) };
#pragma unroll
        for (int nt = 0; nt < 8; ++nt) {
            float2 b = Wc2[(nt * 8 + g) * 68 + ks * 4 + t];
            u32 bb[2] = { __float_as_uint(b.x), __float_as_uint(b.y) };
            mma8(acc[nt], aa, bb);
        }
    }
}

// ============================================================================
// proj_all: LN once; per 64-col weight chunk: gate GEMM, proj GEMM, gated epi.
// smem = As(128x136) + Wc(64x136) = 104448B -> 2 CTAs/SM.
// ============================================================================
__global__ __launch_bounds__(256, 2) void proj_all_kernel(
    const float* __restrict__ z,
    const float* __restrict__ lnw, const float* __restrict__ lnb,
    const float* __restrict__ b_ap, const float* __restrict__ b_ag,
    const float* __restrict__ b_bp, const float* __restrict__ b_bg,
    const float* __restrict__ b_g)
{
    extern __shared__ float smf[];
    float* As = smf;                 // 128 x 136
    float* Wc = smf + 128 * 136;     // 64 x 136
    const int tid = threadIdx.x;
    const int wid = tid >> 5, lane = tid & 31;
    const int g = lane >> 2, t = lane & 3;
    const int m0 = wid * 16;
    const size_t pair0 = (size_t)blockIdx.x * 128;

    // ---- LN -> As (pair layout) ----
    {
        float4 lw = ((const float4*)lnw)[lane];
        float4 lb = ((const float4*)lnb)[lane];
#pragma unroll 2
        for (int r = 0; r < 16; ++r) {
            int row = wid * 16 + r;
            float4 x = ((const float4*)(z + (pair0 + row) * (size_t)CZ))[lane];
            float m = wsum(x.x + x.y + x.z + x.w) * (1.0f / 128.0f);
            float dx = x.x - m, dy = x.y - m, dz = x.z - m, dw = x.w - m;
            float var = wsum(dx * dx + dy * dy + dz * dz + dw * dw) * (1.0f / 128.0f);
            float rs = rsqrtf(var + 1e-5f);
            float* dst = As + row * 136 + (lane >> 1) * 8 + (lane & 1);
            dst[0] = tf32r(dx * rs * lw.x + lb.x);
            dst[2] = tf32r(dy * rs * lw.y + lb.y);
            dst[4] = tf32r(dz * rs * lw.z + lb.z);
            dst[6] = tf32r(dw * rs * lw.w + lb.w);
        }
    }

    const float2* As2 = (const float2*)As;
    const float2* Wc2 = (const float2*)Wc;
    const int aoff = (m0 + g) * 68 + t;
    const int r = m0 + g;

    float accg[8][4], accp[8][4];

    // ---- a then b ----
#pragma unroll 1
    for (int sel = 0; sel < 2; ++sel) {
        const int imgP = sel * 2, imgG = sel * 2 + 1;
        const float* bp = sel ? b_bp : b_ap;
        const float* bg = sel ? b_bg : b_ag;
        float* __restrict__ dst = sel ? g_B : g_A;
#pragma unroll 1
        for (int cb = 0; cb < 128; cb += 64) {
            __syncthreads();
            loadWc(Wc, imgG, cb, tid);
            __syncthreads();
            gemm64(As2, Wc2, aoff, g, t, accg);
            __syncthreads();
            loadWc(Wc, imgP, cb, tid);
            __syncthreads();
            gemm64(As2, Wc2, aoff, g, t, accp);
#pragma unroll
            for (int nt = 0; nt < 8; ++nt) {
                int c = cb + nt * 8 + 2 * t;
                float2 bpv = *(const float2*)(bp + c);
                float2 bgv = *(const float2*)(bg + c);
                float* d0 = dst + (size_t)c * NPAIR + pair0;
                float* d1 = dst + (size_t)(c + 1) * NPAIR + pair0;
                d0[r]     = tf32r(sigm(accg[nt][0] + bgv.x) * (accp[nt][0] + bpv.x));
                d1[r]     = tf32r(sigm(accg[nt][1] + bgv.y) * (accp[nt][1] + bpv.y));
                d0[r + 8] = tf32r(sigm(accg[nt][2] + bgv.x) * (accp[nt][2] + bpv.x));
                d1[r + 8] = tf32r(sigm(accg[nt][3] + bgv.y) * (accp[nt][3] + bpv.y));
            }
        }
    }

    // ---- gate g ----
#pragma unroll 1
    for (int cb = 0; cb < 128; cb += 64) {
        __syncthreads();
        loadWc(Wc, 4, cb, tid);
        __syncthreads();
        gemm64(As2, Wc2, aoff, g, t, accg);
#pragma unroll
        for (int nt = 0; nt < 8; ++nt) {
            int c = cb + nt * 8 + 2 * t;
            float2 bgv = *(const float2*)(b_g + c);
            float* d0 = g_G + (size_t)c * NPAIR + pair0;
            float* d1 = g_G + (size_t)(c + 1) * NPAIR + pair0;
            d0[r]     = sigm(accg[nt][0] + bgv.x);
            d1[r]     = sigm(accg[nt][1] + bgv.y);
            d0[r + 8] = sigm(accg[nt][2] + bgv.x);
            d1[r + 8] = sigm(accg[nt][3] + bgv.y);
        }
    }
}

// ============================================================================
// tri: t[c][i][j] = sum_k a[c][i][k]*b[c][j][k]; 128x128 tile, K chunks of 32,
// single-buffer pair layout (row stride 40 floats = 20 f2, conflict-free).
// smem 40KB static -> 2 CTAs/SM (reg-limited).
// ============================================================================
__global__ __launch_bounds__(256, 2) void tri_kernel()
{
    __shared__ float smf[2 * 128 * 40];
    float2* A2 = (float2*)smf;
    float2* B2 = (float2*)(smf + 128 * 40);
    const int tid = threadIdx.x;
    const int wid = tid >> 5, lane = tid & 31;
    const int g = lane >> 2, t = lane & 3;
    const int m0 = (wid & 3) * 32, n0 = (wid >> 2) * 64;
    const int c  = blockIdx.z;
    const int i0 = blockIdx.y * 128;
    const int j0 = blockIdx.x * 128;
    const float* __restrict__ asrc = g_A + (size_t)c * NPAIR + (size_t)i0 * NROW;
    const float* __restrict__ bsrc = g_B + (size_t)c * NPAIR + (size_t)j0 * NROW;

    float acc[2][8][4];
#pragma unroll
    for (int i = 0; i < 2; ++i)
#pragma unroll
        for (int j = 0; j < 8; ++j)
#pragma unroll
            for (int q = 0; q < 4; ++q) acc[i][j][q] = 0.f;

    const int aoff = (m0 + g) * 20 + t;
    int boff[8];
#pragma unroll
    for (int nt = 0; nt < 8; ++nt) boff[nt] = (n0 + nt * 8 + g) * 20 + t;

#pragma unroll 1
    for (int kc = 0; kc < 16; ++kc) {
        if (kc) __syncthreads();
        const int k0 = kc * 32;
#pragma unroll
        for (int it = 0; it < 4; ++it) {
            int lin = it * 256 + tid, row = lin >> 3, q = lin & 7;
            float4 va = *(const float4*)(asrc + (size_t)row * NROW + k0 + q * 4);
            float4 vb = *(const float4*)(bsrc + (size_t)row * NROW + k0 + q * 4);
            float* pa = smf + row * 40 + (q >> 1) * 8 + (q & 1);
            float* pb = smf + 128 * 40 + row * 40 + (q >> 1) * 8 + (q & 1);
            pa[0] = va.x; pa[2] = va.y; pa[4] = va.z; pa[6] = va.w;
            pb[0] = vb.x; pb[2] = vb.y; pb[4] = vb.z; pb[6] = vb.w;
        }
        __syncthreads();
#pragma unroll
        for (int ks = 0; ks < 4; ++ks) {
            float2 a00 = A2[aoff + ks * 4];
            float2 a01 = A2[aoff + ks * 4 + 160];   // +8 rows
            float2 a10 = A2[aoff + ks * 4 + 320];   // +16 rows
            float2 a11 = A2[aoff + ks * 4 + 480];   // +24 rows
            u32 aa0[4] = { __float_as_uint(a00.x), __float_as_uint(a01.x),
                           __float_as_uint(a00.y), __float_as_uint(a01.y) };
            u32 aa1[4] = { __float_as_uint(a10.x), __float_as_uint(a11.x),
                           __float_as_uint(a10.y), __float_as_uint(a11.y) };
#pragma unroll
            for (int nt = 0; nt < 8; ++nt) {
                float2 b = B2[boff[nt] + ks * 4];
                u32 bb[2] = { __float_as_uint(b.x), __float_as_uint(b.y) };
                mma8(acc[0][nt], aa0, bb);
                mma8(acc[1][nt], aa1, bb);
            }
        }
    }

    float* __restrict__ tdst = g_T + (size_t)c * NPAIR;
#pragma unroll
    for (int mt = 0; mt < 2; ++mt) {
        int r = i0 + m0 + mt * 16 + g;
#pragma unroll
        for (int nt = 0; nt < 8; ++nt) {
            int cl = j0 + n0 + nt * 8 + 2 * t;
            *(float2*)(tdst + (size_t)r * NROW + cl) =
                make_float2(acc[mt][nt][0], acc[mt][nt][1]);
            *(float2*)(tdst + (size_t)(r + 8) * NROW + cl) =
                make_float2(acc[mt][nt][2], acc[mt][nt][3]);
        }
    }
}

// ============================================================================
// final: out[pair][cz] = g * (LN_c(t) @ Wz + bz). 64-pair tiles, grid 4096.
// smem = As(128x72) + Ws(128x136) + stats = 109056B -> 2 CTAs/SM.
// ============================================================================
__global__ __launch_bounds__(256, 2) void final_kernel(
    const float* __restrict__ lnw, const float* __restrict__ lnb,
    const float* __restrict__ bz, float* __restrict__ out)
{
    extern __shared__ float smf[];
    float* As = smf;                 // [128 c][72 pair] k-major
    float* Ws = smf + 128 * 72;      // 128 x 136 pair layout
    float* PS = Ws + 128 * 136;      // 256
    float* PQ = PS + 256;            // 256
    float* MS = PQ + 256;            // 64
    float* RS = MS + 64;             // 64
    const int tid = threadIdx.x;
    const int wid = tid >> 5, lane = tid & 31;
    const int g = lane >> 2, t = lane & 3;
    const int m0 = (wid & 3) * 16, n0 = (wid >> 2) * 64;
    const int p = tid & 63, ch = tid >> 6;
    const size_t pair0 = (size_t)blockIdx.x * 64;

    // weight image (full 128 rows)
    {
        const float4* src = (const float4*)(g_wt + 5 * 16384);
#pragma unroll
        for (int it = 0; it < 16; ++it) {
            int lin = it * 256 + tid;
            int row = lin >> 5, q = lin & 31;
            ((float4*)Ws)[row * 34 + q] = src[row * 32 + q];
        }
    }

    // gather t over c + partial stats
    float s = 0.f, qq = 0.f;
#pragma unroll 4
    for (int cc = 0; cc < 32; ++cc) {
        int c = ch * 32 + cc;
        float v = g_T[(size_t)c * NPAIR + pair0 + p];
        As[c * 72 + p] = v;
        s += v; qq += v * v;
    }
    PS[tid] = s; PQ[tid] = qq;
    __syncthreads();
    if (tid < 64) {
        float ss = PS[tid] + PS[tid + 64] + PS[tid + 128] + PS[tid + 192];
        float sq = PQ[tid] + PQ[tid + 64] + PQ[tid + 128] + PQ[tid + 192];
        float m = ss * (1.0f / 128.0f);
        MS[tid] = m;
        RS[tid] = rsqrtf(fmaxf(sq * (1.0f / 128.0f) - m * m, 0.f) + 1e-5f);
    }
    __syncthreads();

    // normalize in place
    {
        float mp = MS[p], rp = RS[p];
#pragma unroll 4
        for (int cc = 0; cc < 32; ++cc) {
            int c = ch * 32 + cc;
            float lw = __ldg(lnw + c), lb = __ldg(lnb + c);
            As[c * 72 + p] = tf32r((As[c * 72 + p] - mp) * rp * lw + lb);
        }
    }
    __syncthreads();

    // GEMM: warp tile m16 x n64, K=128; A k-major [c][72]
    float acc[8][4];
#pragma unroll
    for (int i = 0; i < 8; ++i)
#pragma unroll
        for (int q = 0; q < 4; ++q) acc[i][q] = 0.f;

    const float2* Ws2 = (const float2*)Ws;
#pragma unroll
    for (int ks = 0; ks < 16; ++ks) {
        const int k0 = ks * 8;
        const float* ap = As + (k0 + t) * 72 + m0 + g;
        u32 aa[4] = { __float_as_uint(ap[0]),      __float_as_uint(ap[8]),
                      __float_as_uint(ap[4 * 72]), __float_as_uint(ap[4 * 72 + 8]) };
#pragma unroll
        for (int nt = 0; nt < 8; ++nt) {
            float2 b = Ws2[(n0 + nt * 8 + g) * 68 + ks * 4 + t];
            u32 bb[2] = { __float_as_uint(b.x), __float_as_uint(b.y) };
            mma8(acc[nt], aa, bb);
        }
    }

    const int r = m0 + g;
#pragma unroll
    for (int nt = 0; nt < 8; ++nt) {
        int c = n0 + nt * 8 + 2 * t;
        float2 bzv = *(const float2*)(bz + c);
        float gv00 = g_G[(size_t)c * NPAIR + pair0 + r];
        float gv01 = g_G[(size_t)(c + 1) * NPAIR + pair0 + r];
        float gv10 = g_G[(size_t)c * NPAIR + pair0 + r + 8];
        float gv11 = g_G[(size_t)(c + 1) * NPAIR + pair0 + r + 8];
        *(float2*)(out + (pair0 + r) * (size_t)CZ + c) =
            make_float2(gv00 * (acc[nt][0] + bzv.x), gv01 * (acc[nt][1] + bzv.y));
        *(float2*)(out + (pair0 + r + 8) * (size_t)CZ + c) =
            make_float2(gv10 * (acc[nt][2] + bzv.x), gv11 * (acc[nt][3] + bzv.y));
    }
}

// ============================================================================
// kernel_launch
// ============================================================================
extern "C" void kernel_launch(void* const* d_in, const int* in_sizes, int n_in,
                              void* d_out, int out_size)
{
    const float* z        = (const float*)d_in[0];
    const float* ln_in_w  = (const float*)d_in[1];
    const float* ln_in_b  = (const float*)d_in[2];
    const float* ln_out_w = (const float*)d_in[3];
    const float* ln_out_b = (const float*)d_in[4];
    const float* w_ap     = (const float*)d_in[5];
    const float* b_ap     = (const float*)d_in[6];
    const float* w_ag     = (const float*)d_in[7];
    const float* b_ag     = (const float*)d_in[8];
    const float* w_bp     = (const float*)d_in[9];
    const float* b_bp     = (const float*)d_in[10];
    const float* w_bg     = (const float*)d_in[11];
    const float* b_bg     = (const float*)d_in[12];
    const float* w_g      = (const float*)d_in[13];
    const float* b_g      = (const float*)d_in[14];
    const float* w_z      = (const float*)d_in[15];
    const float* b_z      = (const float*)d_in[16];
    float* out = (float*)d_out;

    const int PROJ_SMEM = (128 * 136 + 64 * 136) * 4;               // 104448
    const int FIN_SMEM  = (128 * 72 + 128 * 136 + 640) * 4;         // 109056

    cudaFuncSetAttribute(proj_all_kernel, cudaFuncAttributeMaxDynamicSharedMemorySize, PROJ_SMEM);
    cudaFuncSetAttribute(final_kernel,    cudaFuncAttributeMaxDynamicSharedMemorySize, FIN_SMEM);

    dim3 pgrid(64, 6);
    prep_w<<<pgrid, 256>>>(w_ap, w_ag, w_bp, w_bg, w_g, w_z);

    proj_all_kernel<<<NPAIR / 128, 256, PROJ_SMEM>>>(
        z, ln_in_w, ln_in_b, b_ap, b_ag, b_bp, b_bg, b_g);

    dim3 tgrid(4, 4, 128);
    tri_kernel<<<tgrid, 256>>>();

    final_kernel<<<NPAIR / 64, 256, FIN_SMEM>>>(ln_out_w, ln_out_b, b_z, out);
}